// round 1
// baseline (speedup 1.0000x reference)
#include <cuda_runtime.h>
#include <math.h>

#define N_NODES 50000
#define N_EDGES 800000
#define DIM     64
#define N_LAYERS 5

// Scratch (no allocations allowed -> __device__ globals)
__device__ float g_agg[N_NODES * DIM];     // (1+eps)*h + sum of neighbors
__device__ float g_h[N_NODES * DIM];       // current layer activations
__device__ float g_pooled[N_LAYERS * DIM]; // per-layer sum over nodes (mean applied at end)

// ---------------------------------------------------------------------------
// Init: agg = x, pooled = 0
// ---------------------------------------------------------------------------
__global__ void k_init(const float4* __restrict__ x)
{
    int i = blockIdx.x * blockDim.x + threadIdx.x;
    if (i < N_NODES * DIM / 4)
        reinterpret_cast<float4*>(g_agg)[i] = x[i];
    if (i < N_LAYERS * DIM)
        g_pooled[i] = 0.0f;
}

// ---------------------------------------------------------------------------
// Scatter-add: for each edge e, agg[dst[e]] += h[src[e]]
// 16 threads per edge, each handles one float4 chunk (gather is float4,
// scatter is 4 scalar atomics for this round).
// ---------------------------------------------------------------------------
__global__ void k_scatter(const float* __restrict__ x,
                          const int* __restrict__ src,
                          const int* __restrict__ dst,
                          int use_x)
{
    int idx = blockIdx.x * blockDim.x + threadIdx.x;
    if (idx >= N_EDGES * 16) return;
    int e = idx >> 4;
    int c = idx & 15;

    const float* hsrc = use_x ? x : g_h;

    int s = __ldg(src + e);
    int d = __ldg(dst + e);

    float4 v = reinterpret_cast<const float4*>(hsrc)[s * 16 + c];
    float* a = g_agg + d * DIM + c * 4;
    atomicAdd(a + 0, v.x);
    atomicAdd(a + 1, v.y);
    atomicAdd(a + 2, v.z);
    atomicAdd(a + 3, v.w);
}

// ---------------------------------------------------------------------------
// Fused 3-stage MLP (relu(relu(relu(agg@W0)@W1)@W2)) + h/agg writeback +
// pooled-sum accumulation.
//
// Block = 256 threads = 4 groups of 64. Each group processes NB=8 nodes.
// Inputs live in SMEM as [k][n] so one LDS.128 broadcast feeds 4 nodes.
// Accumulators are packed f32x2 (Blackwell FFMA2) -> 2 nodes per FMA instr.
// ---------------------------------------------------------------------------
#define NB 8
#define GROUPS 4
#define NODES_PER_BLOCK (GROUPS * NB)

__global__ __launch_bounds__(256) void k_mlp(const float* __restrict__ W, int layer)
{
    __shared__ __align__(16) float Ws[DIM * DIM];            // 16 KB, one stage at a time
    __shared__ __align__(16) float bufA[GROUPS][DIM][NB];    // 8 KB
    __shared__ __align__(16) float bufB[GROUPS][DIM][NB];    // 8 KB
    __shared__ float poolsh[DIM];

    int tid = threadIdx.x;
    int g   = tid >> 6;   // group 0..3
    int t   = tid & 63;   // output-feature lane 0..63
    int base = blockIdx.x * NODES_PER_BLOCK + g * NB;

    // Load input rows: feature t of nodes base..base+7 -> bufA[g][t][n]
#pragma unroll
    for (int n = 0; n < NB; n++) {
        int node = base + n;
        bufA[g][t][n] = (node < N_NODES) ? g_agg[node * DIM + t] : 0.0f;
    }
    if (tid < DIM) poolsh[tid] = 0.0f;

    const float* Wbase = W + (size_t)layer * 3 * DIM * DIM;

    float* inb  = &bufA[0][0][0];
    float* outb = &bufB[0][0][0];
    float psum = 0.0f;

    for (int s = 0; s < 3; s++) {
        __syncthreads();
        // Stage weight load (16 floats / thread)
        const float* Wst = Wbase + s * DIM * DIM;
#pragma unroll
        for (int i = 0; i < DIM * DIM / 256; i++)
            Ws[i * 256 + tid] = Wst[i * 256 + tid];
        __syncthreads();

        // acc[j] packs 2 nodes: (n=2j, n=2j+1)
        unsigned long long acc0 = 0ull, acc1 = 0ull, acc2 = 0ull, acc3 = 0ull;
        const unsigned long long* in2 =
            reinterpret_cast<const unsigned long long*>(inb + g * DIM * NB);

#pragma unroll 8
        for (int k = 0; k < DIM; k++) {
            unsigned int wb = __float_as_uint(Ws[k * DIM + t]);
            unsigned long long wp;
            asm("mov.b64 %0, {%1, %1};" : "=l"(wp) : "r"(wb));
            unsigned long long i0 = in2[k * 4 + 0];
            unsigned long long i1 = in2[k * 4 + 1];
            unsigned long long i2 = in2[k * 4 + 2];
            unsigned long long i3 = in2[k * 4 + 3];
            asm("fma.rn.f32x2 %0, %1, %2, %0;" : "+l"(acc0) : "l"(i0), "l"(wp));
            asm("fma.rn.f32x2 %0, %1, %2, %0;" : "+l"(acc1) : "l"(i1), "l"(wp));
            asm("fma.rn.f32x2 %0, %1, %2, %0;" : "+l"(acc2) : "l"(i2), "l"(wp));
            asm("fma.rn.f32x2 %0, %1, %2, %0;" : "+l"(acc3) : "l"(i3), "l"(wp));
        }

        // Unpack + ReLU
        float2 a0 = *reinterpret_cast<float2*>(&acc0);
        float2 a1 = *reinterpret_cast<float2*>(&acc1);
        float2 a2 = *reinterpret_cast<float2*>(&acc2);
        float2 a3 = *reinterpret_cast<float2*>(&acc3);
        float o[NB];
        o[0] = fmaxf(a0.x, 0.0f); o[1] = fmaxf(a0.y, 0.0f);
        o[2] = fmaxf(a1.x, 0.0f); o[3] = fmaxf(a1.y, 0.0f);
        o[4] = fmaxf(a2.x, 0.0f); o[5] = fmaxf(a2.y, 0.0f);
        o[6] = fmaxf(a3.x, 0.0f); o[7] = fmaxf(a3.y, 0.0f);

        // Write to the other buffer (layout [k=t][n])
        float* ob = outb + (g * DIM + t) * NB;
#pragma unroll
        for (int n = 0; n < NB; n++) ob[n] = o[n];

        if (s == 2) {
            // Epilogue: write h and agg(=h seed for next layer), pooled sum
            float ps = 0.0f;
#pragma unroll
            for (int n = 0; n < NB; n++) {
                int node = base + n;
                if (node < N_NODES) {
                    g_h[node * DIM + t]   = o[n];
                    g_agg[node * DIM + t] = o[n];
                    ps += o[n];
                }
            }
            psum = ps;
        }
        // swap buffers
        float* tmp = inb; inb = outb; outb = tmp;
    }

    __syncthreads();
    atomicAdd(&poolsh[t], psum);
    __syncthreads();
    if (tid < DIM)
        atomicAdd(&g_pooled[layer * DIM + tid], poolsh[tid]);
}

// ---------------------------------------------------------------------------
// Final: logits_l = dot(pooled_l / N, Wl_l); out = sigmoid(sum_l logits_l)
// ---------------------------------------------------------------------------
__global__ void k_final(const float* __restrict__ Wl, float* __restrict__ out)
{
    __shared__ float red[128];
    int tid = threadIdx.x;
    float s = 0.0f;
    for (int i = tid; i < N_LAYERS * DIM; i += 128)
        s += g_pooled[i] * Wl[i];
    red[tid] = s;
    __syncthreads();
    for (int o = 64; o > 0; o >>= 1) {
        if (tid < o) red[tid] += red[tid + o];
        __syncthreads();
    }
    if (tid == 0) {
        float v = red[0] / (float)N_NODES;
        out[0] = 1.0f / (1.0f + expf(-v));
    }
}

// ---------------------------------------------------------------------------
// Launch
// ---------------------------------------------------------------------------
extern "C" void kernel_launch(void* const* d_in, const int* in_sizes, int n_in,
                              void* d_out, int out_size)
{
    const float* x   = (const float*)d_in[0];
    const float* W   = (const float*)d_in[1];
    const float* Wl  = (const float*)d_in[2];
    const int*   src = (const int*)d_in[3];
    const int*   dst = (const int*)d_in[4];
    float*       out = (float*)d_out;

    (void)in_sizes; (void)n_in; (void)out_size;

    k_init<<<(N_NODES * DIM / 4 + 255) / 256, 256>>>((const float4*)x);

    int scatter_blocks = (N_EDGES * 16 + 255) / 256;
    int mlp_blocks     = (N_NODES + NODES_PER_BLOCK - 1) / NODES_PER_BLOCK;

    for (int l = 0; l < N_LAYERS; l++) {
        k_scatter<<<scatter_blocks, 256>>>(x, src, dst, l == 0 ? 1 : 0);
        k_mlp<<<mlp_blocks, 256>>>(W, l);
    }
    k_final<<<1, 128>>>(Wl, out);
}

// round 2
// speedup vs baseline: 1.6699x; 1.6699x over previous
#include <cuda_runtime.h>
#include <math.h>

#define N_NODES 50000
#define N_EDGES 800000
#define DIM     64
#define N_LAYERS 5

// Scratch (no allocations allowed -> __device__ globals)
__device__ float g_agg[N_NODES * DIM];     // (1+eps)*h + sum of neighbors
__device__ float g_h[N_NODES * DIM];       // current layer activations
__device__ float g_pooled[N_LAYERS * DIM]; // per-layer sum over nodes (mean at end)

// ---------------------------------------------------------------------------
// Init: agg = x, pooled = 0
// ---------------------------------------------------------------------------
__global__ void k_init(const float4* __restrict__ x)
{
    int i = blockIdx.x * blockDim.x + threadIdx.x;
    if (i < N_NODES * DIM / 4)
        reinterpret_cast<float4*>(g_agg)[i] = x[i];
    if (i < N_LAYERS * DIM)
        g_pooled[i] = 0.0f;
}

// ---------------------------------------------------------------------------
// Scatter-add: for each edge e, agg[dst[e]] += h[src[e]]
// 16 threads per edge, one float4 chunk each. Gather = LDG.128, scatter =
// single red.global.add.v4.f32 (REDG.128) instead of 4 scalar atomics.
// ---------------------------------------------------------------------------
__global__ void k_scatter(const float* __restrict__ x,
                          const int* __restrict__ src,
                          const int* __restrict__ dst,
                          int use_x)
{
    int idx = blockIdx.x * blockDim.x + threadIdx.x;
    if (idx >= N_EDGES * 16) return;
    int e = idx >> 4;
    int c = idx & 15;

    const float* hsrc = use_x ? x : g_h;

    int s = __ldg(src + e);
    int d = __ldg(dst + e);

    float4 v = reinterpret_cast<const float4*>(hsrc)[s * 16 + c];
    float* a = g_agg + d * DIM + c * 4;
    asm volatile("red.global.add.v4.f32 [%0], {%1, %2, %3, %4};"
                 :: "l"(a), "f"(v.x), "f"(v.y), "f"(v.z), "f"(v.w)
                 : "memory");
}

// ---------------------------------------------------------------------------
// Fused 3-stage MLP (relu x3) + h/agg writeback + pooled-sum accumulation.
// Block = 256 threads = 4 groups of 64; each group handles NB=8 nodes.
// Packed f32x2 FMA: 2 nodes per instruction.
// ---------------------------------------------------------------------------
#define NB 8
#define GROUPS 4
#define NODES_PER_BLOCK (GROUPS * NB)

__global__ __launch_bounds__(256) void k_mlp(const float* __restrict__ W, int layer)
{
    __shared__ __align__(16) float Ws[DIM * DIM];            // 16 KB
    __shared__ __align__(16) float bufA[GROUPS][DIM][NB];    // 8 KB
    __shared__ __align__(16) float bufB[GROUPS][DIM][NB];    // 8 KB
    __shared__ float poolsh[DIM];

    int tid = threadIdx.x;
    int g   = tid >> 6;
    int t   = tid & 63;
    int base = blockIdx.x * NODES_PER_BLOCK + g * NB;

#pragma unroll
    for (int n = 0; n < NB; n++) {
        int node = base + n;
        bufA[g][t][n] = (node < N_NODES) ? g_agg[node * DIM + t] : 0.0f;
    }
    if (tid < DIM) poolsh[tid] = 0.0f;

    const float* Wbase = W + (size_t)layer * 3 * DIM * DIM;

    float* inb  = &bufA[0][0][0];
    float* outb = &bufB[0][0][0];
    float psum = 0.0f;

    for (int s = 0; s < 3; s++) {
        __syncthreads();
        const float* Wst = Wbase + s * DIM * DIM;
#pragma unroll
        for (int i = 0; i < DIM * DIM / 256; i++)
            Ws[i * 256 + tid] = Wst[i * 256 + tid];
        __syncthreads();

        unsigned long long acc0 = 0ull, acc1 = 0ull, acc2 = 0ull, acc3 = 0ull;
        const unsigned long long* in2 =
            reinterpret_cast<const unsigned long long*>(inb + g * DIM * NB);

#pragma unroll 8
        for (int k = 0; k < DIM; k++) {
            unsigned int wb = __float_as_uint(Ws[k * DIM + t]);
            unsigned long long wp;
            asm("mov.b64 %0, {%1, %1};" : "=l"(wp) : "r"(wb));
            unsigned long long i0 = in2[k * 4 + 0];
            unsigned long long i1 = in2[k * 4 + 1];
            unsigned long long i2 = in2[k * 4 + 2];
            unsigned long long i3 = in2[k * 4 + 3];
            asm("fma.rn.f32x2 %0, %1, %2, %0;" : "+l"(acc0) : "l"(i0), "l"(wp));
            asm("fma.rn.f32x2 %0, %1, %2, %0;" : "+l"(acc1) : "l"(i1), "l"(wp));
            asm("fma.rn.f32x2 %0, %1, %2, %0;" : "+l"(acc2) : "l"(i2), "l"(wp));
            asm("fma.rn.f32x2 %0, %1, %2, %0;" : "+l"(acc3) : "l"(i3), "l"(wp));
        }

        float2 a0 = *reinterpret_cast<float2*>(&acc0);
        float2 a1 = *reinterpret_cast<float2*>(&acc1);
        float2 a2 = *reinterpret_cast<float2*>(&acc2);
        float2 a3 = *reinterpret_cast<float2*>(&acc3);
        float o[NB];
        o[0] = fmaxf(a0.x, 0.0f); o[1] = fmaxf(a0.y, 0.0f);
        o[2] = fmaxf(a1.x, 0.0f); o[3] = fmaxf(a1.y, 0.0f);
        o[4] = fmaxf(a2.x, 0.0f); o[5] = fmaxf(a2.y, 0.0f);
        o[6] = fmaxf(a3.x, 0.0f); o[7] = fmaxf(a3.y, 0.0f);

        float* ob = outb + (g * DIM + t) * NB;
#pragma unroll
        for (int n = 0; n < NB; n++) ob[n] = o[n];

        if (s == 2) {
            float ps = 0.0f;
#pragma unroll
            for (int n = 0; n < NB; n++) {
                int node = base + n;
                if (node < N_NODES) {
                    g_h[node * DIM + t]   = o[n];
                    g_agg[node * DIM + t] = o[n];
                    ps += o[n];
                }
            }
            psum = ps;
        }
        float* tmp = inb; inb = outb; outb = tmp;
    }

    __syncthreads();
    atomicAdd(&poolsh[t], psum);
    __syncthreads();
    if (tid < DIM)
        atomicAdd(&g_pooled[layer * DIM + tid], poolsh[tid]);
}

// ---------------------------------------------------------------------------
// Final: out = sigmoid( sum_l dot(pooled_l / N, Wl_l) )
// ---------------------------------------------------------------------------
__global__ void k_final(const float* __restrict__ Wl, float* __restrict__ out)
{
    __shared__ float red[128];
    int tid = threadIdx.x;
    float s = 0.0f;
    for (int i = tid; i < N_LAYERS * DIM; i += 128)
        s += g_pooled[i] * Wl[i];
    red[tid] = s;
    __syncthreads();
    for (int o = 64; o > 0; o >>= 1) {
        if (tid < o) red[tid] += red[tid + o];
        __syncthreads();
    }
    if (tid == 0) {
        float v = red[0] / (float)N_NODES;
        out[0] = 1.0f / (1.0f + expf(-v));
    }
}

// ---------------------------------------------------------------------------
// Launch
// ---------------------------------------------------------------------------
extern "C" void kernel_launch(void* const* d_in, const int* in_sizes, int n_in,
                              void* d_out, int out_size)
{
    const float* x   = (const float*)d_in[0];
    const float* W   = (const float*)d_in[1];
    const float* Wl  = (const float*)d_in[2];
    const int*   src = (const int*)d_in[3];
    const int*   dst = (const int*)d_in[4];
    float*       out = (float*)d_out;

    (void)in_sizes; (void)n_in; (void)out_size;

    k_init<<<(N_NODES * DIM / 4 + 255) / 256, 256>>>((const float4*)x);

    int scatter_blocks = (N_EDGES * 16 + 255) / 256;
    int mlp_blocks     = (N_NODES + NODES_PER_BLOCK - 1) / NODES_PER_BLOCK;

    for (int l = 0; l < N_LAYERS; l++) {
        k_scatter<<<scatter_blocks, 256>>>(x, src, dst, l == 0 ? 1 : 0);
        k_mlp<<<mlp_blocks, 256>>>(W, l);
    }
    k_final<<<1, 128>>>(Wl, out);
}

// round 4
// speedup vs baseline: 1.9271x; 1.1540x over previous
#include <cuda_runtime.h>
#include <math.h>

#define N_NODES 50000
#define N_EDGES 800000
#define DIM     64
#define N_LAYERS 5

// Scratch (no allocations allowed -> __device__ globals)
__device__ float g_agg[N_NODES * DIM];
__device__ float g_h[N_NODES * DIM];
__device__ float g_pooled[N_LAYERS * DIM];
__device__ int   g_deg[N_NODES];       // degree, then reused as fill cursor
__device__ int   g_off[N_NODES + 1];   // CSR row offsets (by dst)
__device__ int   g_csr[N_EDGES];       // src indices grouped by dst

// ---------------------------------------------------------------------------
// Zero: deg = 0, pooled = 0
// ---------------------------------------------------------------------------
__global__ void k_zero()
{
    int i = blockIdx.x * blockDim.x + threadIdx.x;
    if (i < N_NODES) g_deg[i] = 0;
    if (i < N_LAYERS * DIM) g_pooled[i] = 0.0f;
}

// ---------------------------------------------------------------------------
// CSR build step 1: histogram of dst
// ---------------------------------------------------------------------------
__global__ void k_count(const int* __restrict__ dst)
{
    int e = blockIdx.x * blockDim.x + threadIdx.x;
    if (e < N_EDGES)
        atomicAdd(&g_deg[dst[e]], 1);
}

// ---------------------------------------------------------------------------
// CSR build step 2: exclusive prefix sum over 50000 degrees (1 block).
// Also zeroes deg for reuse as cursor in k_fill.
// ---------------------------------------------------------------------------
#define SCAN_THREADS 1024
#define SCAN_CHUNK   49   // 1024*49 = 50176 >= 50000

__global__ void k_scan()
{
    __shared__ int partial[SCAN_THREADS];
    int tid = threadIdx.x;
    int start = tid * SCAN_CHUNK;

    int s = 0;
    for (int i = 0; i < SCAN_CHUNK; i++) {
        int idx = start + i;
        if (idx < N_NODES) s += g_deg[idx];
    }
    partial[tid] = s;
    __syncthreads();

    // Hillis-Steele inclusive scan
    for (int o = 1; o < SCAN_THREADS; o <<= 1) {
        int v = (tid >= o) ? partial[tid - o] : 0;
        __syncthreads();
        partial[tid] += v;
        __syncthreads();
    }

    int run = (tid > 0) ? partial[tid - 1] : 0;
    for (int i = 0; i < SCAN_CHUNK; i++) {
        int idx = start + i;
        if (idx < N_NODES) {
            int d = g_deg[idx];
            g_off[idx] = run;
            run += d;
            g_deg[idx] = 0;   // reset for cursor use
        }
    }
    if (tid == SCAN_THREADS - 1) g_off[N_NODES] = N_EDGES;
}

// ---------------------------------------------------------------------------
// CSR build step 3: bucket-fill src indices by dst
// ---------------------------------------------------------------------------
__global__ void k_fill(const int* __restrict__ src, const int* __restrict__ dst)
{
    int e = blockIdx.x * blockDim.x + threadIdx.x;
    if (e < N_EDGES) {
        int d = dst[e];
        int p = atomicAdd(&g_deg[d], 1);
        g_csr[g_off[d] + p] = src[e];
    }
}

// ---------------------------------------------------------------------------
// Gather: agg[v] = h[v] + sum_{u in N(v)} h[u]   (plain loads/stores, no atomics)
// 16 threads per node, one float4 chunk each.
// NOTE: source buffer selected INSIDE the kernel — taking the address of a
// __device__ global in host code yields the host shadow symbol (R3 bug).
// ---------------------------------------------------------------------------
__global__ void k_gather(const float4* __restrict__ x, int use_x)
{
    int idx = blockIdx.x * blockDim.x + threadIdx.x;
    if (idx >= N_NODES * 16) return;
    int v = idx >> 4;
    int c = idx & 15;

    const float4* hsrc = use_x ? x : reinterpret_cast<const float4*>(g_h);

    float4 acc = hsrc[v * 16 + c];
    float4 acc2 = make_float4(0.f, 0.f, 0.f, 0.f);

    int j = g_off[v];
    int end = g_off[v + 1];

    for (; j + 2 <= end; j += 2) {
        int s0 = g_csr[j];
        int s1 = g_csr[j + 1];
        float4 a = hsrc[s0 * 16 + c];
        float4 b = hsrc[s1 * 16 + c];
        acc.x += a.x;  acc.y += a.y;  acc.z += a.z;  acc.w += a.w;
        acc2.x += b.x; acc2.y += b.y; acc2.z += b.z; acc2.w += b.w;
    }
    if (j < end) {
        float4 a = hsrc[g_csr[j] * 16 + c];
        acc.x += a.x; acc.y += a.y; acc.z += a.z; acc.w += a.w;
    }
    acc.x += acc2.x; acc.y += acc2.y; acc.z += acc2.z; acc.w += acc2.w;

    reinterpret_cast<float4*>(g_agg)[v * 16 + c] = acc;
}

// ---------------------------------------------------------------------------
// Fused 3-stage MLP (relu x3) + h writeback + pooled-sum accumulation.
// Block = 128 threads = 2 groups of 64; each group handles NB=16 nodes.
// Inputs in SMEM as [k][n] (row stride NBP=20 floats), 16B LDS;
// accumulators are packed f32x2 -> 8 FFMA2 per k => FMA-bound.
// ---------------------------------------------------------------------------
#define NB  16
#define NBP 20
#define GROUPS 2
#define NODES_PER_BLOCK (GROUPS * NB)

__global__ __launch_bounds__(128) void k_mlp(const float* __restrict__ W, int layer)
{
    __shared__ __align__(16) float Ws[DIM * DIM];                 // 16 KB
    __shared__ __align__(16) float bufA[GROUPS * DIM * NBP];      // 10 KB
    __shared__ __align__(16) float bufB[GROUPS * DIM * NBP];      // 10 KB
    __shared__ float poolsh[DIM];

    int tid = threadIdx.x;
    int g   = tid >> 6;
    int t   = tid & 63;
    int base = blockIdx.x * NODES_PER_BLOCK + g * NB;

    // Input load: feature t of nodes base..base+15 -> bufA[g][t][n]
#pragma unroll
    for (int n = 0; n < NB; n++) {
        int node = base + n;
        bufA[(g * DIM + t) * NBP + n] = (node < N_NODES) ? g_agg[node * DIM + t] : 0.0f;
    }
    if (tid < DIM) poolsh[tid] = 0.0f;

    const float* Wbase = W + (size_t)layer * 3 * DIM * DIM;

    float* inb  = bufA;
    float* outb = bufB;
    float psum = 0.0f;

    for (int s = 0; s < 3; s++) {
        __syncthreads();
        // Stage weight load: 32 floats per thread (128 threads)
        const float4* Wst = reinterpret_cast<const float4*>(Wbase + s * DIM * DIM);
        float4* Wsv = reinterpret_cast<float4*>(Ws);
#pragma unroll
        for (int i = 0; i < DIM * DIM / 4 / 128; i++)
            Wsv[i * 128 + tid] = Wst[i * 128 + tid];
        __syncthreads();

        unsigned long long acc0 = 0ull, acc1 = 0ull, acc2 = 0ull, acc3 = 0ull;
        unsigned long long acc4 = 0ull, acc5 = 0ull, acc6 = 0ull, acc7 = 0ull;
        const ulonglong2* in2 =
            reinterpret_cast<const ulonglong2*>(inb + g * DIM * NBP);

#pragma unroll 4
        for (int k = 0; k < DIM; k++) {
            unsigned int wb = __float_as_uint(Ws[k * DIM + t]);
            unsigned long long wp;
            asm("mov.b64 %0, {%1, %1};" : "=l"(wp) : "r"(wb));
            ulonglong2 q0 = in2[k * 5 + 0];
            ulonglong2 q1 = in2[k * 5 + 1];
            ulonglong2 q2 = in2[k * 5 + 2];
            ulonglong2 q3 = in2[k * 5 + 3];
            asm("fma.rn.f32x2 %0, %1, %2, %0;" : "+l"(acc0) : "l"(q0.x), "l"(wp));
            asm("fma.rn.f32x2 %0, %1, %2, %0;" : "+l"(acc1) : "l"(q0.y), "l"(wp));
            asm("fma.rn.f32x2 %0, %1, %2, %0;" : "+l"(acc2) : "l"(q1.x), "l"(wp));
            asm("fma.rn.f32x2 %0, %1, %2, %0;" : "+l"(acc3) : "l"(q1.y), "l"(wp));
            asm("fma.rn.f32x2 %0, %1, %2, %0;" : "+l"(acc4) : "l"(q2.x), "l"(wp));
            asm("fma.rn.f32x2 %0, %1, %2, %0;" : "+l"(acc5) : "l"(q2.y), "l"(wp));
            asm("fma.rn.f32x2 %0, %1, %2, %0;" : "+l"(acc6) : "l"(q3.x), "l"(wp));
            asm("fma.rn.f32x2 %0, %1, %2, %0;" : "+l"(acc7) : "l"(q3.y), "l"(wp));
        }

        // Unpack + ReLU
        float o[NB];
        {
            float2 a;
            a = *reinterpret_cast<float2*>(&acc0); o[0]  = fmaxf(a.x, 0.f); o[1]  = fmaxf(a.y, 0.f);
            a = *reinterpret_cast<float2*>(&acc1); o[2]  = fmaxf(a.x, 0.f); o[3]  = fmaxf(a.y, 0.f);
            a = *reinterpret_cast<float2*>(&acc2); o[4]  = fmaxf(a.x, 0.f); o[5]  = fmaxf(a.y, 0.f);
            a = *reinterpret_cast<float2*>(&acc3); o[6]  = fmaxf(a.x, 0.f); o[7]  = fmaxf(a.y, 0.f);
            a = *reinterpret_cast<float2*>(&acc4); o[8]  = fmaxf(a.x, 0.f); o[9]  = fmaxf(a.y, 0.f);
            a = *reinterpret_cast<float2*>(&acc5); o[10] = fmaxf(a.x, 0.f); o[11] = fmaxf(a.y, 0.f);
            a = *reinterpret_cast<float2*>(&acc6); o[12] = fmaxf(a.x, 0.f); o[13] = fmaxf(a.y, 0.f);
            a = *reinterpret_cast<float2*>(&acc7); o[14] = fmaxf(a.x, 0.f); o[15] = fmaxf(a.y, 0.f);
        }

        // Write row t of the other buffer: 4 x STS.128
        float* ob = outb + (g * DIM + t) * NBP;
        reinterpret_cast<float4*>(ob)[0] = make_float4(o[0],  o[1],  o[2],  o[3]);
        reinterpret_cast<float4*>(ob)[1] = make_float4(o[4],  o[5],  o[6],  o[7]);
        reinterpret_cast<float4*>(ob)[2] = make_float4(o[8],  o[9],  o[10], o[11]);
        reinterpret_cast<float4*>(ob)[3] = make_float4(o[12], o[13], o[14], o[15]);

        if (s == 2) {
            float ps = 0.0f;
#pragma unroll
            for (int n = 0; n < NB; n++) {
                int node = base + n;
                if (node < N_NODES) {
                    g_h[node * DIM + t] = o[n];
                    ps += o[n];
                }
            }
            psum = ps;
        }
        float* tmp = inb; inb = outb; outb = tmp;
    }

    __syncthreads();
    atomicAdd(&poolsh[t], psum);
    __syncthreads();
    if (tid < DIM)
        atomicAdd(&g_pooled[layer * DIM + tid], poolsh[tid]);
}

// ---------------------------------------------------------------------------
// Final: out = sigmoid( sum_l dot(pooled_l / N, Wl_l) )
// ---------------------------------------------------------------------------
__global__ void k_final(const float* __restrict__ Wl, float* __restrict__ out)
{
    __shared__ float red[128];
    int tid = threadIdx.x;
    float s = 0.0f;
    for (int i = tid; i < N_LAYERS * DIM; i += 128)
        s += g_pooled[i] * Wl[i];
    red[tid] = s;
    __syncthreads();
    for (int o = 64; o > 0; o >>= 1) {
        if (tid < o) red[tid] += red[tid + o];
        __syncthreads();
    }
    if (tid == 0) {
        float v = red[0] / (float)N_NODES;
        out[0] = 1.0f / (1.0f + expf(-v));
    }
}

// ---------------------------------------------------------------------------
// Launch
// ---------------------------------------------------------------------------
extern "C" void kernel_launch(void* const* d_in, const int* in_sizes, int n_in,
                              void* d_out, int out_size)
{
    const float* x   = (const float*)d_in[0];
    const float* W   = (const float*)d_in[1];
    const float* Wl  = (const float*)d_in[2];
    const int*   src = (const int*)d_in[3];
    const int*   dst = (const int*)d_in[4];
    float*       out = (float*)d_out;

    (void)in_sizes; (void)n_in; (void)out_size;

    // CSR build (amortized over the 5 layers)
    k_zero<<<(N_NODES + 255) / 256, 256>>>();
    k_count<<<(N_EDGES + 255) / 256, 256>>>(dst);
    k_scan<<<1, SCAN_THREADS>>>();
    k_fill<<<(N_EDGES + 255) / 256, 256>>>(src, dst);

    int gather_blocks = (N_NODES * 16 + 255) / 256;
    int mlp_blocks    = (N_NODES + NODES_PER_BLOCK - 1) / NODES_PER_BLOCK;

    for (int l = 0; l < N_LAYERS; l++) {
        k_gather<<<gather_blocks, 256>>>((const float4*)x, l == 0 ? 1 : 0);
        k_mlp<<<mlp_blocks, 128>>>(W, l);
    }
    k_final<<<1, 128>>>(Wl, out);
}

// round 5
// speedup vs baseline: 2.2428x; 1.1638x over previous
#include <cuda_runtime.h>
#include <math.h>

#define N_NODES 50000
#define N_EDGES 800000
#define DIM     64
#define N_LAYERS 5

#define SCAN_BLK  512
#define SCAN_NBLK ((N_NODES + SCAN_BLK - 1) / SCAN_BLK)   // 98

// Scratch (no allocations allowed -> __device__ globals)
__device__ float g_agg[N_NODES * DIM];
__device__ float g_h[N_NODES * DIM];
__device__ float g_pooled[N_LAYERS * DIM];
__device__ int   g_deg[N_NODES];       // degree, then reused as fill cursor
__device__ int   g_off[N_NODES + 1];   // CSR row offsets (by dst)
__device__ int   g_csr[N_EDGES];       // src indices grouped by dst
__device__ int   g_bsum[SCAN_NBLK];    // per-block degree sums
__device__ int   g_boff[SCAN_NBLK];    // exclusive scan of block sums

// ---------------------------------------------------------------------------
// Zero: deg = 0, pooled = 0
// ---------------------------------------------------------------------------
__global__ void k_zero()
{
    int i = blockIdx.x * blockDim.x + threadIdx.x;
    if (i < N_NODES) g_deg[i] = 0;
    if (i < N_LAYERS * DIM) g_pooled[i] = 0.0f;
}

// ---------------------------------------------------------------------------
// CSR build step 1: histogram of dst
// ---------------------------------------------------------------------------
__global__ void k_count(const int* __restrict__ dst)
{
    int e = blockIdx.x * blockDim.x + threadIdx.x;
    if (e < N_EDGES)
        atomicAdd(&g_deg[dst[e]], 1);
}

// ---------------------------------------------------------------------------
// CSR scan stage A: per-block sums of degrees (full-chip parallel)
// ---------------------------------------------------------------------------
__global__ void k_scan_a()
{
    __shared__ int sh[SCAN_BLK];
    int tid = threadIdx.x;
    int i = blockIdx.x * SCAN_BLK + tid;
    sh[tid] = (i < N_NODES) ? g_deg[i] : 0;
    __syncthreads();
    for (int o = SCAN_BLK / 2; o > 0; o >>= 1) {
        if (tid < o) sh[tid] += sh[tid + o];
        __syncthreads();
    }
    if (tid == 0) g_bsum[blockIdx.x] = sh[0];
}

// ---------------------------------------------------------------------------
// CSR scan stage B: exclusive scan of 98 block sums (tiny, 1 warp)
// ---------------------------------------------------------------------------
__global__ void k_scan_b()
{
    if (threadIdx.x == 0) {
        int run = 0;
        for (int b = 0; b < SCAN_NBLK; b++) {
            g_boff[b] = run;
            run += g_bsum[b];
        }
        g_off[N_NODES] = N_EDGES;
    }
}

// ---------------------------------------------------------------------------
// CSR scan stage C: local exclusive scan + block offset -> g_off; reset deg
// ---------------------------------------------------------------------------
__global__ void k_scan_c()
{
    __shared__ int sh[SCAN_BLK];
    int tid = threadIdx.x;
    int i = blockIdx.x * SCAN_BLK + tid;
    int v = (i < N_NODES) ? g_deg[i] : 0;
    sh[tid] = v;
    __syncthreads();
    // Hillis-Steele inclusive scan over 512
    for (int o = 1; o < SCAN_BLK; o <<= 1) {
        int t = (tid >= o) ? sh[tid - o] : 0;
        __syncthreads();
        sh[tid] += t;
        __syncthreads();
    }
    if (i < N_NODES) {
        int excl = sh[tid] - v;                 // exclusive within block
        g_off[i] = g_boff[blockIdx.x] + excl;
        g_deg[i] = 0;                           // reset for cursor use
    }
}

// ---------------------------------------------------------------------------
// CSR build step 3: bucket-fill src indices by dst
// ---------------------------------------------------------------------------
__global__ void k_fill(const int* __restrict__ src, const int* __restrict__ dst)
{
    int e = blockIdx.x * blockDim.x + threadIdx.x;
    if (e < N_EDGES) {
        int d = dst[e];
        int p = atomicAdd(&g_deg[d], 1);
        g_csr[g_off[d] + p] = src[e];
    }
}

// ---------------------------------------------------------------------------
// Gather: agg[v] = h[v] + sum_{u in N(v)} h[u]   (no atomics)
// 16 threads per node, one float4 chunk each. Source buffer selected INSIDE
// the kernel (host-side &g_h is the shadow symbol -> R3 bug).
// ---------------------------------------------------------------------------
__global__ void k_gather(const float4* __restrict__ x, int use_x)
{
    int idx = blockIdx.x * blockDim.x + threadIdx.x;
    if (idx >= N_NODES * 16) return;
    int v = idx >> 4;
    int c = idx & 15;

    const float4* hsrc = use_x ? x : reinterpret_cast<const float4*>(g_h);

    float4 acc = hsrc[v * 16 + c];
    float4 acc2 = make_float4(0.f, 0.f, 0.f, 0.f);

    int j = g_off[v];
    int end = g_off[v + 1];

    for (; j + 2 <= end; j += 2) {
        int s0 = g_csr[j];
        int s1 = g_csr[j + 1];
        float4 a = hsrc[s0 * 16 + c];
        float4 b = hsrc[s1 * 16 + c];
        acc.x += a.x;  acc.y += a.y;  acc.z += a.z;  acc.w += a.w;
        acc2.x += b.x; acc2.y += b.y; acc2.z += b.z; acc2.w += b.w;
    }
    if (j < end) {
        float4 a = hsrc[g_csr[j] * 16 + c];
        acc.x += a.x; acc.y += a.y; acc.z += a.z; acc.w += a.w;
    }
    acc.x += acc2.x; acc.y += acc2.y; acc.z += acc2.z; acc.w += acc2.w;

    reinterpret_cast<float4*>(g_agg)[v * 16 + c] = acc;
}

// ---------------------------------------------------------------------------
// Fused 3-stage MLP (relu x3) + h writeback + pooled-sum accumulation.
// Block = 128 threads = 2 groups of 64; each group handles NB=16 nodes.
// Packed f32x2 accumulators -> 8 FFMA2 per k => FMA-bound.
// ---------------------------------------------------------------------------
#define NB  16
#define NBP 20
#define GROUPS 2
#define NODES_PER_BLOCK (GROUPS * NB)

__global__ __launch_bounds__(128) void k_mlp(const float* __restrict__ W, int layer)
{
    __shared__ __align__(16) float Ws[DIM * DIM];                 // 16 KB
    __shared__ __align__(16) float bufA[GROUPS * DIM * NBP];      // 10 KB
    __shared__ __align__(16) float bufB[GROUPS * DIM * NBP];      // 10 KB
    __shared__ float poolsh[DIM];

    int tid = threadIdx.x;
    int g   = tid >> 6;
    int t   = tid & 63;
    int base = blockIdx.x * NODES_PER_BLOCK + g * NB;

#pragma unroll
    for (int n = 0; n < NB; n++) {
        int node = base + n;
        bufA[(g * DIM + t) * NBP + n] = (node < N_NODES) ? g_agg[node * DIM + t] : 0.0f;
    }
    if (tid < DIM) poolsh[tid] = 0.0f;

    const float* Wbase = W + (size_t)layer * 3 * DIM * DIM;

    float* inb  = bufA;
    float* outb = bufB;
    float psum = 0.0f;

    for (int s = 0; s < 3; s++) {
        __syncthreads();
        const float4* Wst = reinterpret_cast<const float4*>(Wbase + s * DIM * DIM);
        float4* Wsv = reinterpret_cast<float4*>(Ws);
#pragma unroll
        for (int i = 0; i < DIM * DIM / 4 / 128; i++)
            Wsv[i * 128 + tid] = Wst[i * 128 + tid];
        __syncthreads();

        unsigned long long acc0 = 0ull, acc1 = 0ull, acc2 = 0ull, acc3 = 0ull;
        unsigned long long acc4 = 0ull, acc5 = 0ull, acc6 = 0ull, acc7 = 0ull;
        const ulonglong2* in2 =
            reinterpret_cast<const ulonglong2*>(inb + g * DIM * NBP);

#pragma unroll 4
        for (int k = 0; k < DIM; k++) {
            unsigned int wb = __float_as_uint(Ws[k * DIM + t]);
            unsigned long long wp;
            asm("mov.b64 %0, {%1, %1};" : "=l"(wp) : "r"(wb));
            ulonglong2 q0 = in2[k * 5 + 0];
            ulonglong2 q1 = in2[k * 5 + 1];
            ulonglong2 q2 = in2[k * 5 + 2];
            ulonglong2 q3 = in2[k * 5 + 3];
            asm("fma.rn.f32x2 %0, %1, %2, %0;" : "+l"(acc0) : "l"(q0.x), "l"(wp));
            asm("fma.rn.f32x2 %0, %1, %2, %0;" : "+l"(acc1) : "l"(q0.y), "l"(wp));
            asm("fma.rn.f32x2 %0, %1, %2, %0;" : "+l"(acc2) : "l"(q1.x), "l"(wp));
            asm("fma.rn.f32x2 %0, %1, %2, %0;" : "+l"(acc3) : "l"(q1.y), "l"(wp));
            asm("fma.rn.f32x2 %0, %1, %2, %0;" : "+l"(acc4) : "l"(q2.x), "l"(wp));
            asm("fma.rn.f32x2 %0, %1, %2, %0;" : "+l"(acc5) : "l"(q2.y), "l"(wp));
            asm("fma.rn.f32x2 %0, %1, %2, %0;" : "+l"(acc6) : "l"(q3.x), "l"(wp));
            asm("fma.rn.f32x2 %0, %1, %2, %0;" : "+l"(acc7) : "l"(q3.y), "l"(wp));
        }

        float o[NB];
        {
            float2 a;
            a = *reinterpret_cast<float2*>(&acc0); o[0]  = fmaxf(a.x, 0.f); o[1]  = fmaxf(a.y, 0.f);
            a = *reinterpret_cast<float2*>(&acc1); o[2]  = fmaxf(a.x, 0.f); o[3]  = fmaxf(a.y, 0.f);
            a = *reinterpret_cast<float2*>(&acc2); o[4]  = fmaxf(a.x, 0.f); o[5]  = fmaxf(a.y, 0.f);
            a = *reinterpret_cast<float2*>(&acc3); o[6]  = fmaxf(a.x, 0.f); o[7]  = fmaxf(a.y, 0.f);
            a = *reinterpret_cast<float2*>(&acc4); o[8]  = fmaxf(a.x, 0.f); o[9]  = fmaxf(a.y, 0.f);
            a = *reinterpret_cast<float2*>(&acc5); o[10] = fmaxf(a.x, 0.f); o[11] = fmaxf(a.y, 0.f);
            a = *reinterpret_cast<float2*>(&acc6); o[12] = fmaxf(a.x, 0.f); o[13] = fmaxf(a.y, 0.f);
            a = *reinterpret_cast<float2*>(&acc7); o[14] = fmaxf(a.x, 0.f); o[15] = fmaxf(a.y, 0.f);
        }

        float* ob = outb + (g * DIM + t) * NBP;
        reinterpret_cast<float4*>(ob)[0] = make_float4(o[0],  o[1],  o[2],  o[3]);
        reinterpret_cast<float4*>(ob)[1] = make_float4(o[4],  o[5],  o[6],  o[7]);
        reinterpret_cast<float4*>(ob)[2] = make_float4(o[8],  o[9],  o[10], o[11]);
        reinterpret_cast<float4*>(ob)[3] = make_float4(o[12], o[13], o[14], o[15]);

        if (s == 2) {
            float ps = 0.0f;
#pragma unroll
            for (int n = 0; n < NB; n++) {
                int node = base + n;
                if (node < N_NODES) {
                    g_h[node * DIM + t] = o[n];
                    ps += o[n];
                }
            }
            psum = ps;
        }
        float* tmp = inb; inb = outb; outb = tmp;
    }

    __syncthreads();
    atomicAdd(&poolsh[t], psum);
    __syncthreads();
    if (tid < DIM)
        atomicAdd(&g_pooled[layer * DIM + tid], poolsh[tid]);
}

// ---------------------------------------------------------------------------
// Final: out = sigmoid( sum_l dot(pooled_l / N, Wl_l) )
// ---------------------------------------------------------------------------
__global__ void k_final(const float* __restrict__ Wl, float* __restrict__ out)
{
    __shared__ float red[128];
    int tid = threadIdx.x;
    float s = 0.0f;
    for (int i = tid; i < N_LAYERS * DIM; i += 128)
        s += g_pooled[i] * Wl[i];
    red[tid] = s;
    __syncthreads();
    for (int o = 64; o > 0; o >>= 1) {
        if (tid < o) red[tid] += red[tid + o];
        __syncthreads();
    }
    if (tid == 0) {
        float v = red[0] / (float)N_NODES;
        out[0] = 1.0f / (1.0f + expf(-v));
    }
}

// ---------------------------------------------------------------------------
// Launch
// ---------------------------------------------------------------------------
extern "C" void kernel_launch(void* const* d_in, const int* in_sizes, int n_in,
                              void* d_out, int out_size)
{
    const float* x   = (const float*)d_in[0];
    const float* W   = (const float*)d_in[1];
    const float* Wl  = (const float*)d_in[2];
    const int*   src = (const int*)d_in[3];
    const int*   dst = (const int*)d_in[4];
    float*       out = (float*)d_out;

    (void)in_sizes; (void)n_in; (void)out_size;

    // CSR build (multi-block scan; the 1-block scan was a ~100us serial tail)
    k_zero<<<(N_NODES + 255) / 256, 256>>>();
    k_count<<<(N_EDGES + 255) / 256, 256>>>(dst);
    k_scan_a<<<SCAN_NBLK, SCAN_BLK>>>();
    k_scan_b<<<1, 32>>>();
    k_scan_c<<<SCAN_NBLK, SCAN_BLK>>>();
    k_fill<<<(N_EDGES + 255) / 256, 256>>>(src, dst);

    int gather_blocks = (N_NODES * 16 + 255) / 256;
    int mlp_blocks    = (N_NODES + NODES_PER_BLOCK - 1) / NODES_PER_BLOCK;

    for (int l = 0; l < N_LAYERS; l++) {
        k_gather<<<gather_blocks, 256>>>((const float4*)x, l == 0 ? 1 : 0);
        k_mlp<<<mlp_blocks, 128>>>(W, l);
    }
    k_final<<<1, 128>>>(Wl, out);
}